// round 13
// baseline (speedup 1.0000x reference)
#include <cuda_runtime.h>
#include <cuda_bf16.h>
#include <math.h>
#include <stdint.h>

#define BH    32
#define SEQ   2048
#define DIM   1024
#define NH    16
#define HDIM  64
#define MROWS 4096

// ---------------- device scratch ----------------
__device__ __nv_bfloat16 g_xh[MROWS * DIM], g_xl[MROWS * DIM];
__device__ __nv_bfloat16 g_Wqh[DIM * DIM], g_Wql[DIM * DIM];
__device__ __nv_bfloat16 g_Wkh[DIM * DIM], g_Wkl[DIM * DIM];
__device__ __nv_bfloat16 g_Wvh[DIM * DIM], g_Wvl[DIM * DIM];
__device__ __nv_bfloat16 g_Woh[DIM * DIM], g_Wol[DIM * DIM];
__device__ __nv_bfloat16 g_Qh[BH * SEQ * HDIM], g_Ql[BH * SEQ * HDIM];
__device__ __nv_bfloat16 g_Kh[BH * SEQ * HDIM], g_Kl[BH * SEQ * HDIM];
__device__ __nv_bfloat16 g_Vth[BH * HDIM * SEQ], g_Vtl[BH * HDIM * SEQ];
__device__ __nv_bfloat16 g_Ph[(size_t)BH * SEQ * SEQ], g_Pl[(size_t)BH * SEQ * SEQ];
__device__ float         g_rowsum[BH * SEQ];
__device__ __nv_bfloat16 g_Ah[(size_t)MROWS * DIM], g_Al[(size_t)MROWS * DIM];

// ---------------- helpers ----------------
__device__ __forceinline__ uint32_t smem_u32(const void* p) {
    uint32_t a;
    asm("{ .reg .u64 t; cvta.to.shared.u64 t, %1; cvt.u32.u64 %0, t; }" : "=r"(a) : "l"(p));
    return a;
}
__device__ __forceinline__ void cp16(uint32_t s, const void* g) {
    asm volatile("cp.async.cg.shared.global [%0], [%1], 16;" :: "r"(s), "l"(g));
}
__device__ __forceinline__ void mma_bf16(float* d, const uint32_t* a, const uint32_t* b) {
    asm volatile(
        "mma.sync.aligned.m16n8k16.row.col.f32.bf16.bf16.f32 "
        "{%0,%1,%2,%3}, {%4,%5,%6,%7}, {%8,%9}, {%0,%1,%2,%3};"
        : "+f"(d[0]), "+f"(d[1]), "+f"(d[2]), "+f"(d[3])
        : "r"(a[0]), "r"(a[1]), "r"(a[2]), "r"(a[3]), "r"(b[0]), "r"(b[1]));
}
__device__ __forceinline__ void split2(float v0, float v1, uint32_t& h, uint32_t& l) {
    __nv_bfloat16 h0 = __float2bfloat16(v0), h1 = __float2bfloat16(v1);
    h = ((uint32_t)__bfloat16_as_ushort(h1) << 16) | __bfloat16_as_ushort(h0);
    __nv_bfloat16 l0 = __float2bfloat16(v0 - __bfloat162float(h0));
    __nv_bfloat16 l1 = __float2bfloat16(v1 - __bfloat162float(h1));
    l = ((uint32_t)__bfloat16_as_ushort(l1) << 16) | __bfloat16_as_ushort(l0);
}

// ---------------- GEMM parameter block ----------------
struct GP {
    const __nv_bfloat16 *Ah, *Al, *Bh, *Bl;
    long strideA, bStrideA, strideB, bStrideB;
    const float* bias;
    float scale;
    int Ktot, mode;
    __nv_bfloat16 *outH, *outL;
    float *outF, *rowsum;
};

// ---------------- split conversion kernels ----------------
__global__ __launch_bounds__(256) void split_kernel(const float* __restrict__ in,
                                                    __nv_bfloat16* __restrict__ h,
                                                    __nv_bfloat16* __restrict__ l, int n) {
    int i = blockIdx.x * 256 + threadIdx.x;
    if (i < n) {
        float v = in[i];
        __nv_bfloat16 hi = __float2bfloat16(v);
        h[i] = hi;
        l[i] = __float2bfloat16(v - __bfloat162float(hi));
    }
}

struct WS { const float* W[4]; __nv_bfloat16 *th[4], *tl[4]; };
__global__ __launch_bounds__(256) void wsplit4_kernel(WS ws) {
    __shared__ float t[32][33];
    const float* W = ws.W[blockIdx.z];
    __nv_bfloat16* th = ws.th[blockIdx.z];
    __nv_bfloat16* tl = ws.tl[blockIdx.z];
    int n0 = blockIdx.x * 32, k0 = blockIdx.y * 32;
    int tx = threadIdx.x & 31, ty = threadIdx.x >> 5;
#pragma unroll
    for (int r = ty; r < 32; r += 8)
        t[r][tx] = W[(size_t)(k0 + r) * DIM + n0 + tx];
    __syncthreads();
#pragma unroll
    for (int r = ty; r < 32; r += 8) {
        float v = t[tx][r];
        __nv_bfloat16 hi = __float2bfloat16(v);
        size_t idx = (size_t)(n0 + r) * DIM + k0 + tx;
        th[idx] = hi;
        tl[idx] = __float2bfloat16(v - __bfloat162float(hi));
    }
}

// ---------------- mma.sync split-bf16 GEMM: CTA 64x64, 4 warps, term-major MMA ----
// modes: 0 Q/K head-split hi/lo, 1 V transposed hi/lo, 2 fp32 out (+bias),
//        3 exp(scores) -> P hi/lo + atomic rowsum, 4 merged / rowsum
__global__ __launch_bounds__(128, 5) void gemm_kernel(GP P)
{
    extern __shared__ char smem[];
    constexpr int NT = 4;
    constexpr int ROWB = 80;
    constexpr int A_H = 0;
    constexpr int A_L = 64 * ROWB;
    constexpr int B_H = 2 * 64 * ROWB;
    constexpr int B_L = 3 * 64 * ROWB;
    constexpr int STAGE = 4 * 64 * ROWB;      // 20480

    const int tid = threadIdx.x;
    const int w = tid >> 5, lane = tid & 31;
    const int g = lane >> 2, t = lane & 3;
    const int wm = w & 1, wn = w >> 1;
    const int bx = blockIdx.x, by = blockIdx.y, bz = blockIdx.z;
    const __nv_bfloat16* Ah = P.Ah + (size_t)bz * P.bStrideA;
    const __nv_bfloat16* Al = P.Al + (size_t)bz * P.bStrideA;
    const __nv_bfloat16* Bh = P.Bh + (size_t)bz * P.bStrideB;
    const __nv_bfloat16* Bl = P.Bl + (size_t)bz * P.bStrideB;
    const long strideA = P.strideA, strideB = P.strideB;

    const int m0 = by * 64, n0 = bx * 64;
    const int nch = P.Ktot >> 5;
    const uint32_t sb = smem_u32(smem);

    float acc[2][NT][4];
#pragma unroll
    for (int i = 0; i < 2; i++)
#pragma unroll
        for (int j = 0; j < NT; j++)
#pragma unroll
            for (int k = 0; k < 4; k++) acc[i][j][k] = 0.f;

    auto stage_load = [&](int buf, int c) {
        const int k0 = c << 5;
        const uint32_t so = sb + buf * STAGE;
#pragma unroll
        for (int i = tid; i < 256; i += 128) {
            int r = i >> 2, cc = i & 3;
            uint32_t off = r * ROWB + cc * 16;
            cp16(so + A_H + off, Ah + (size_t)(m0 + r) * strideA + k0 + cc * 8);
            cp16(so + A_L + off, Al + (size_t)(m0 + r) * strideA + k0 + cc * 8);
            cp16(so + B_H + off, Bh + (size_t)(n0 + r) * strideB + k0 + cc * 8);
            cp16(so + B_L + off, Bl + (size_t)(n0 + r) * strideB + k0 + cc * 8);
        }
        asm volatile("cp.async.commit_group;");
    };

    stage_load(0, 0);
    for (int c = 0; c < nch; c++) {
        const int buf = c & 1;
        if (c + 1 < nch) {
            stage_load(buf ^ 1, c + 1);
            asm volatile("cp.async.wait_group 1;");
        } else {
            asm volatile("cp.async.wait_group 0;");
        }
        __syncthreads();

        const char* s = smem + buf * STAGE;
#pragma unroll
        for (int ks = 0; ks < 2; ks++) {
            const int kb = ks * 32 + t * 4;
            uint32_t ah[2][4], al[2][4], bh[NT][2], bl[NT][2];
#pragma unroll
            for (int mt = 0; mt < 2; mt++) {
                const char* p = s + (wm * 32 + mt * 16 + g) * ROWB + kb;
                ah[mt][0] = *(const uint32_t*)(p + A_H);
                ah[mt][1] = *(const uint32_t*)(p + A_H + 8 * ROWB);
                ah[mt][2] = *(const uint32_t*)(p + A_H + 16);
                ah[mt][3] = *(const uint32_t*)(p + A_H + 8 * ROWB + 16);
                al[mt][0] = *(const uint32_t*)(p + A_L);
                al[mt][1] = *(const uint32_t*)(p + A_L + 8 * ROWB);
                al[mt][2] = *(const uint32_t*)(p + A_L + 16);
                al[mt][3] = *(const uint32_t*)(p + A_L + 8 * ROWB + 16);
            }
#pragma unroll
            for (int nt = 0; nt < NT; nt++) {
                const char* p = s + (wn * 32 + nt * 8 + g) * ROWB + kb;
                bh[nt][0] = *(const uint32_t*)(p + B_H);
                bh[nt][1] = *(const uint32_t*)(p + B_H + 16);
                bl[nt][0] = *(const uint32_t*)(p + B_L);
                bl[nt][1] = *(const uint32_t*)(p + B_L + 16);
            }
            // term-major: 8 independent MMAs between accumulator reuses
#pragma unroll
            for (int mt = 0; mt < 2; mt++)
#pragma unroll
                for (int nt = 0; nt < NT; nt++)
                    mma_bf16(acc[mt][nt], ah[mt], bh[nt]);
#pragma unroll
            for (int mt = 0; mt < 2; mt++)
#pragma unroll
                for (int nt = 0; nt < NT; nt++)
                    mma_bf16(acc[mt][nt], ah[mt], bl[nt]);
#pragma unroll
            for (int mt = 0; mt < 2; mt++)
#pragma unroll
                for (int nt = 0; nt < NT; nt++)
                    mma_bf16(acc[mt][nt], al[mt], bh[nt]);
        }
        __syncthreads();
    }

    // ---------------- epilogue ----------------
    const int mode = P.mode;
    if (mode == 3) {
        float rs[2][2] = {};
#pragma unroll
        for (int mt = 0; mt < 2; mt++)
#pragma unroll
            for (int nt = 0; nt < NT; nt++)
#pragma unroll
                for (int p = 0; p < 2; p++) {
                    float e0 = __expf(acc[mt][nt][2 * p + 0]);
                    float e1 = __expf(acc[mt][nt][2 * p + 1]);
                    acc[mt][nt][2 * p + 0] = e0;
                    acc[mt][nt][2 * p + 1] = e1;
                    rs[mt][p] += e0 + e1;
                }
#pragma unroll
        for (int mt = 0; mt < 2; mt++)
#pragma unroll
            for (int p = 0; p < 2; p++) {
                int row = m0 + wm * 32 + mt * 16 + g + 8 * p;
#pragma unroll
                for (int nt = 0; nt < NT; nt++) {
                    int col = n0 + wn * 32 + nt * 8 + 2 * t;
                    size_t ofs = (size_t)bz * SEQ * SEQ + (size_t)row * SEQ + col;
                    uint32_t hh, ll;
                    split2(acc[mt][nt][2 * p + 0], acc[mt][nt][2 * p + 1], hh, ll);
                    *(uint32_t*)(P.outH + ofs) = hh;
                    *(uint32_t*)(P.outL + ofs) = ll;
                }
                float s2 = rs[mt][p];
                s2 += __shfl_xor_sync(0xffffffffu, s2, 1);
                s2 += __shfl_xor_sync(0xffffffffu, s2, 2);
                if (t == 0) atomicAdd(&P.rowsum[bz * SEQ + row], s2);
            }
        return;
    }

#pragma unroll
    for (int mt = 0; mt < 2; mt++)
#pragma unroll
        for (int nt = 0; nt < NT; nt++)
#pragma unroll
            for (int p = 0; p < 2; p++) {
                int row = m0 + wm * 32 + mt * 16 + g + 8 * p;
                int col = n0 + wn * 32 + nt * 8 + 2 * t;
                float v0 = acc[mt][nt][2 * p + 0];
                float v1 = acc[mt][nt][2 * p + 1];
                if (mode == 0 || mode == 1) {
                    int b = row >> 11, sq = row & (SEQ - 1);
                    v0 = (v0 + P.bias[col]) * P.scale;
                    v1 = (v1 + P.bias[col + 1]) * P.scale;
#pragma unroll
                    for (int e = 0; e < 2; e++) {
                        int cc = col + e;
                        float v = e ? v1 : v0;
                        int h = cc >> 6, hd = cc & (HDIM - 1);
                        __nv_bfloat16 hi = __float2bfloat16(v);
                        __nv_bfloat16 lo = __float2bfloat16(v - __bfloat162float(hi));
                        size_t idx = (mode == 0)
                            ? ((((size_t)b * NH + h) * SEQ + sq) * HDIM + hd)
                            : ((((size_t)b * NH + h) * HDIM + hd) * SEQ + sq);
                        P.outH[idx] = hi;
                        P.outL[idx] = lo;
                    }
                } else if (mode == 2) {
                    *(float2*)(P.outF + (size_t)row * DIM + col)
                        = make_float2(v0 + P.bias[col], v1 + P.bias[col + 1]);
                } else {  // mode 4
                    float inv = 1.0f / P.rowsum[bz * SEQ + row];
                    v0 *= inv;
                    v1 *= inv;
                    int b = bz >> 4, h = bz & (NH - 1);
                    size_t base = ((size_t)b * SEQ + row) * DIM + h * HDIM + col;
                    uint32_t hh, ll;
                    split2(v0, v1, hh, ll);
                    *(uint32_t*)(P.outH + base) = hh;
                    *(uint32_t*)(P.outL + base) = ll;
                }
            }
}

// ---------------- host ----------------
static void* sym(const void* s) { void* p; cudaGetSymbolAddress(&p, s); return p; }

extern "C" void kernel_launch(void* const* d_in, const int* in_sizes, int n_in,
                              void* d_out, int out_size)
{
    const float* x  = (const float*)d_in[0];
    const float* Wq = (const float*)d_in[1];
    const float* bq = (const float*)d_in[2];
    const float* Wk = (const float*)d_in[3];
    const float* bk = (const float*)d_in[4];
    const float* Wv = (const float*)d_in[5];
    const float* bv = (const float*)d_in[6];
    const float* Wo = (const float*)d_in[7];
    const float* bo = (const float*)d_in[8];
    float* out = (float*)d_out;

    constexpr int SMEM = 2 * 4 * 64 * 80;   // 40960
    cudaFuncSetAttribute(gemm_kernel, cudaFuncAttributeMaxDynamicSharedMemorySize, SMEM);

    __nv_bfloat16 *xh = (__nv_bfloat16*)sym(g_xh), *xl = (__nv_bfloat16*)sym(g_xl);
    __nv_bfloat16 *wqh = (__nv_bfloat16*)sym(g_Wqh), *wql = (__nv_bfloat16*)sym(g_Wql);
    __nv_bfloat16 *wkh = (__nv_bfloat16*)sym(g_Wkh), *wkl = (__nv_bfloat16*)sym(g_Wkl);
    __nv_bfloat16 *wvh = (__nv_bfloat16*)sym(g_Wvh), *wvl = (__nv_bfloat16*)sym(g_Wvl);
    __nv_bfloat16 *woh = (__nv_bfloat16*)sym(g_Woh), *wol = (__nv_bfloat16*)sym(g_Wol);
    __nv_bfloat16 *qh = (__nv_bfloat16*)sym(g_Qh), *ql = (__nv_bfloat16*)sym(g_Ql);
    __nv_bfloat16 *kh = (__nv_bfloat16*)sym(g_Kh), *kl = (__nv_bfloat16*)sym(g_Kl);
    __nv_bfloat16 *vth = (__nv_bfloat16*)sym(g_Vth), *vtl = (__nv_bfloat16*)sym(g_Vtl);
    __nv_bfloat16 *pwh = (__nv_bfloat16*)sym(g_Ph), *pwl = (__nv_bfloat16*)sym(g_Pl);
    __nv_bfloat16 *ah = (__nv_bfloat16*)sym(g_Ah), *al = (__nv_bfloat16*)sym(g_Al);
    float* rsum = (float*)sym(g_rowsum);

    cudaMemsetAsync(rsum, 0, BH * SEQ * sizeof(float), 0);

    split_kernel<<<(MROWS * DIM + 255) / 256, 256>>>(x, xh, xl, MROWS * DIM);

    WS ws;
    ws.W[0] = Wq;  ws.th[0] = wqh;  ws.tl[0] = wql;
    ws.W[1] = Wk;  ws.th[1] = wkh;  ws.tl[1] = wkl;
    ws.W[2] = Wv;  ws.th[2] = wvh;  ws.tl[2] = wvl;
    ws.W[3] = Wo;  ws.th[3] = woh;  ws.tl[3] = wol;
    wsplit4_kernel<<<dim3(DIM / 32, DIM / 32, 4), 256>>>(ws);

    dim3 blk(128);
    dim3 gproj(DIM / 64, MROWS / 64, 1);   // 16 x 64 = 1024 blocks

    GP q = {xh, xl, wqh, wql, DIM, 0, DIM, 0, bq, 0.125f, DIM, 0, qh, ql, nullptr, nullptr};
    GP k = {xh, xl, wkh, wkl, DIM, 0, DIM, 0, bk, 1.0f,   DIM, 0, kh, kl, nullptr, nullptr};
    GP v = {xh, xl, wvh, wvl, DIM, 0, DIM, 0, bv, 1.0f,   DIM, 1, vth, vtl, nullptr, nullptr};
    GP s = {qh, ql, kh, kl, HDIM, (long)SEQ * HDIM, HDIM, (long)SEQ * HDIM,
            nullptr, 1.0f, HDIM, 3, pwh, pwl, nullptr, rsum};
    GP av = {pwh, pwl, vth, vtl, SEQ, (long)SEQ * SEQ, SEQ, (long)HDIM * SEQ,
             nullptr, 1.0f, SEQ, 4, ah, al, nullptr, rsum};
    GP o = {ah, al, woh, wol, DIM, 0, DIM, 0, bo, 1.0f, DIM, 2,
            nullptr, nullptr, out, nullptr};

    gemm_kernel<<<gproj, blk, SMEM>>>(q);
    gemm_kernel<<<gproj, blk, SMEM>>>(k);
    gemm_kernel<<<gproj, blk, SMEM>>>(v);
    gemm_kernel<<<dim3(SEQ / 64, SEQ / 64, BH), blk, SMEM>>>(s);
    gemm_kernel<<<dim3(1, SEQ / 64, BH), blk, SMEM>>>(av);
    gemm_kernel<<<gproj, blk, SMEM>>>(o);
}

// round 14
// speedup vs baseline: 1.3563x; 1.3563x over previous
#include <cuda_runtime.h>
#include <cuda_bf16.h>
#include <math.h>
#include <stdint.h>

#define BH    32
#define SEQ   2048
#define DIM   1024
#define NH    16
#define HDIM  64
#define MROWS 4096

// ---------------- device scratch (16B-aligned for uint4/cp.async access) ----------
__device__ __align__(16) __nv_bfloat16 g_xh[MROWS * DIM], g_xl[MROWS * DIM];
__device__ __align__(16) __nv_bfloat16 g_Wqh[DIM * DIM], g_Wql[DIM * DIM];
__device__ __align__(16) __nv_bfloat16 g_Wkh[DIM * DIM], g_Wkl[DIM * DIM];
__device__ __align__(16) __nv_bfloat16 g_Wvh[DIM * DIM], g_Wvl[DIM * DIM];
__device__ __align__(16) __nv_bfloat16 g_Woh[DIM * DIM], g_Wol[DIM * DIM];
__device__ __align__(16) __nv_bfloat16 g_Qh[BH * SEQ * HDIM], g_Ql[BH * SEQ * HDIM];
__device__ __align__(16) __nv_bfloat16 g_Kh[BH * SEQ * HDIM], g_Kl[BH * SEQ * HDIM];
__device__ __align__(16) __nv_bfloat16 g_Vth[BH * HDIM * SEQ], g_Vtl[BH * HDIM * SEQ];
__device__ __align__(16) __nv_bfloat16 g_Ph[(size_t)BH * SEQ * SEQ], g_Pl[(size_t)BH * SEQ * SEQ];
__device__ float g_rowsum[BH * SEQ];
__device__ __align__(16) __nv_bfloat16 g_Ah[(size_t)MROWS * DIM], g_Al[(size_t)MROWS * DIM];

// ---------------- helpers ----------------
__device__ __forceinline__ uint32_t smem_u32(const void* p) {
    uint32_t a;
    asm("{ .reg .u64 t; cvta.to.shared.u64 t, %1; cvt.u32.u64 %0, t; }" : "=r"(a) : "l"(p));
    return a;
}
__device__ __forceinline__ void cp16(uint32_t s, const void* g) {
    asm volatile("cp.async.cg.shared.global [%0], [%1], 16;" :: "r"(s), "l"(g));
}
__device__ __forceinline__ void mma_bf16(float* d, const uint32_t* a, const uint32_t* b) {
    asm volatile(
        "mma.sync.aligned.m16n8k16.row.col.f32.bf16.bf16.f32 "
        "{%0,%1,%2,%3}, {%4,%5,%6,%7}, {%8,%9}, {%0,%1,%2,%3};"
        : "+f"(d[0]), "+f"(d[1]), "+f"(d[2]), "+f"(d[3])
        : "r"(a[0]), "r"(a[1]), "r"(a[2]), "r"(a[3]), "r"(b[0]), "r"(b[1]));
}
#define LDS128(r, addr) \
    asm volatile("ld.shared.v4.b32 {%0,%1,%2,%3}, [%4];" \
        : "=r"((r)[0]), "=r"((r)[1]), "=r"((r)[2]), "=r"((r)[3]) : "r"(addr))

__device__ __forceinline__ void split2(float v0, float v1, uint32_t& h, uint32_t& l) {
    __nv_bfloat16 h0 = __float2bfloat16(v0), h1 = __float2bfloat16(v1);
    h = ((uint32_t)__bfloat16_as_ushort(h1) << 16) | __bfloat16_as_ushort(h0);
    __nv_bfloat16 l0 = __float2bfloat16(v0 - __bfloat162float(h0));
    __nv_bfloat16 l1 = __float2bfloat16(v1 - __bfloat162float(h1));
    l = ((uint32_t)__bfloat16_as_ushort(l1) << 16) | __bfloat16_as_ushort(l0);
}

// fragment-tiled index maps (element index within one tensor; c/k LSB = byte pair pos)
__device__ __forceinline__ size_t atile(int m, int k, int ktiles) {
    int r = m & 15, c = k & 15;
    return ((((size_t)(m >> 4)) * ktiles + (k >> 4)) << 8)
         + ((((r & 7) << 2) + ((c & 7) >> 1)) << 3)
         + (((r >> 3) + ((c >> 3) << 1)) << 1) + (c & 1);
}
__device__ __forceinline__ size_t btile(int n, int k, int ktiles) {
    int nn = n & 15, kk = k & 15;
    return ((((size_t)(n >> 4)) * ktiles + (k >> 4)) << 8)
         + ((((nn & 7) << 2) + ((kk & 7) >> 1)) << 3)
         + (((kk >> 3) + ((nn >> 3) << 1)) << 1) + (kk & 1);
}

// ---------------- GEMM parameter block ----------------
struct GP {
    const __nv_bfloat16 *Ah, *Al, *Bh, *Bl;
    long bStrideA, bStrideB;
    const float* bias;
    float scale;
    int Ktot, mode;
    __nv_bfloat16 *outH, *outL;
    float *outF, *rowsum;
};

// ---------------- conversion kernels (write fragment-tiled layouts) ----------------
// x [MROWS, DIM] -> A-tiled hi/lo. One thread = one lane of one tile (16B out each).
__global__ __launch_bounds__(256) void splitx_kernel(const float* __restrict__ x) {
    int slot = blockIdx.x * 256 + threadIdx.x;   // tiles*32 slots
    int tile = slot >> 5, lane = slot & 31;
    int tm = tile >> 6, tk = tile & 63;          // DIM/16 = 64 ktiles
    int rg = lane >> 2, tq = lane & 3;
    const float* b0 = x + (size_t)(tm * 16 + rg) * DIM + tk * 16 + tq * 2;
    float2 f00 = *(const float2*)b0;
    float2 f10 = *(const float2*)(b0 + 8 * DIM);
    float2 f01 = *(const float2*)(b0 + 8);
    float2 f11 = *(const float2*)(b0 + 8 * DIM + 8);
    uint4 hv, lv;
    split2(f00.x, f00.y, hv.x, lv.x);
    split2(f10.x, f10.y, hv.y, lv.y);
    split2(f01.x, f01.y, hv.z, lv.z);
    split2(f11.x, f11.y, hv.w, lv.w);
    ((uint4*)g_xh)[slot] = hv;
    ((uint4*)g_xl)[slot] = lv;
}

// W [DIM(k), DIM(n)] -> B-tiled W^T hi/lo (B[n][k] = W[k][n])
struct WS { const float* W[4]; __nv_bfloat16 *th[4], *tl[4]; };
__global__ __launch_bounds__(256) void wsplit4_kernel(WS ws) {
    int slot = blockIdx.x * 256 + threadIdx.x;   // 131072 per weight
    int tile = slot >> 5, lane = slot & 31;
    int tn = tile >> 6, tk = tile & 63;
    int g = lane >> 2, tq = lane & 3;
    const float* W = ws.W[blockIdx.z];
    const float* c0 = W + (size_t)(tk * 16 + tq * 2) * DIM + tn * 16 + g;
    float w00 = c0[0],           w01 = c0[DIM];            // k=2t,2t+1  n=g
    float w10 = c0[8 * DIM],     w11 = c0[9 * DIM];        // k=2t+8,+9  n=g
    float w20 = c0[8],           w21 = c0[DIM + 8];        // k=2t,2t+1  n=g+8
    float w30 = c0[8 * DIM + 8], w31 = c0[9 * DIM + 8];    // k=2t+8,+9  n=g+8
    uint4 hv, lv;
    split2(w00, w01, hv.x, lv.x);
    split2(w10, w11, hv.y, lv.y);
    split2(w20, w21, hv.z, lv.z);
    split2(w30, w31, hv.w, lv.w);
    ((uint4*)ws.th[blockIdx.z])[slot] = hv;
    ((uint4*)ws.tl[blockIdx.z])[slot] = lv;
}

// ---------------- GEMM: CTA 64x64, 4 warps, fragment-tiled smem, LDS.128 frags ----
// modes: 0 Q (A-tiled head-split), 5 K (B-tiled head-split), 1 Vt (B-tiled),
//        2 fp32 out (+bias), 3 exp->P (A-tiled) + rowsum, 4 attn (A-tiled) / rowsum
__global__ __launch_bounds__(128, 5) void gemm_kernel(GP P)
{
    extern __shared__ char smem[];
    constexpr int STAGE = 16384;   // Ahi 4K | Alo 4K | Bhi 4K | Blo 4K

    const int tid = threadIdx.x;
    const int w = tid >> 5, lane = tid & 31;
    const int g = lane >> 2, t = lane & 3;
    const int wm = w & 1, wn = w >> 1;
    const int bx = blockIdx.x, by = blockIdx.y, bz = blockIdx.z;
    const __nv_bfloat16* Ah = P.Ah + (size_t)bz * P.bStrideA;
    const __nv_bfloat16* Al = P.Al + (size_t)bz * P.bStrideA;
    const __nv_bfloat16* Bh = P.Bh + (size_t)bz * P.bStrideB;
    const __nv_bfloat16* Bl = P.Bl + (size_t)bz * P.bStrideB;

    const int m0 = by * 64, n0 = bx * 64;
    const int ktiles = P.Ktot >> 4;
    const int nch = P.Ktot >> 5;
    const uint32_t sb = smem_u32(smem);

    float acc[2][4][4];
#pragma unroll
    for (int i = 0; i < 2; i++)
#pragma unroll
        for (int j = 0; j < 4; j++)
#pragma unroll
            for (int k = 0; k < 4; k++) acc[i][j][k] = 0.f;

    auto stage_load = [&](int buf, int c) {
        const uint32_t so = sb + buf * STAGE;
        const int kt = c << 1;
#pragma unroll
        for (int i = tid; i < 512; i += 128) {         // A planes: hi,lo x 8 tiles
            int pl = i >> 8, seg = i & 255, tl2 = seg >> 5, s = seg & 31;
            size_t go = (((size_t)((m0 >> 4) + (tl2 >> 1))) * ktiles + kt + (tl2 & 1)) * 256
                      + s * 8;
            cp16(so + pl * 4096 + tl2 * 512 + s * 16, (pl ? Al : Ah) + go);
        }
#pragma unroll
        for (int i = tid; i < 512; i += 128) {         // B planes
            int pl = i >> 8, seg = i & 255, tl2 = seg >> 5, s = seg & 31;
            size_t go = (((size_t)((n0 >> 4) + (tl2 >> 1))) * ktiles + kt + (tl2 & 1)) * 256
                      + s * 8;
            cp16(so + 8192 + pl * 4096 + tl2 * 512 + s * 16, (pl ? Bl : Bh) + go);
        }
        asm volatile("cp.async.commit_group;");
    };

    stage_load(0, 0);
    for (int c = 0; c < nch; c++) {
        const int buf = c & 1;
        if (c + 1 < nch) {
            stage_load(buf ^ 1, c + 1);
            asm volatile("cp.async.wait_group 1;");
        } else {
            asm volatile("cp.async.wait_group 0;");
        }
        __syncthreads();

        const uint32_t so = sb + buf * STAGE;
#pragma unroll
        for (int ks = 0; ks < 2; ks++) {
            uint32_t ah[2][4], al[2][4], b4h[2][4], b4l[2][4];
#pragma unroll
            for (int mt = 0; mt < 2; mt++) {
                uint32_t a = so + ((((wm * 2 + mt) << 1) + ks) << 9) + (lane << 4);
                LDS128(ah[mt], a);
                LDS128(al[mt], a + 4096);
            }
#pragma unroll
            for (int p2 = 0; p2 < 2; p2++) {
                uint32_t b = so + 8192 + ((((wn * 2 + p2) << 1) + ks) << 9) + (lane << 4);
                LDS128(b4h[p2], b);
                LDS128(b4l[p2], b + 4096);
            }
#pragma unroll
            for (int mt = 0; mt < 2; mt++)
#pragma unroll
                for (int nt = 0; nt < 4; nt++)
                    mma_bf16(acc[mt][nt], ah[mt], &b4h[nt >> 1][(nt & 1) << 1]);
#pragma unroll
            for (int mt = 0; mt < 2; mt++)
#pragma unroll
                for (int nt = 0; nt < 4; nt++)
                    mma_bf16(acc[mt][nt], ah[mt], &b4l[nt >> 1][(nt & 1) << 1]);
#pragma unroll
            for (int mt = 0; mt < 2; mt++)
#pragma unroll
                for (int nt = 0; nt < 4; nt++)
                    mma_bf16(acc[mt][nt], al[mt], &b4h[nt >> 1][(nt & 1) << 1]);
        }
        __syncthreads();
    }

    // ---------------- epilogue ----------------
    const int mode = P.mode;
    if (mode == 3) {
        float rs[2][2] = {};
#pragma unroll
        for (int mt = 0; mt < 2; mt++)
#pragma unroll
            for (int nt = 0; nt < 4; nt++)
#pragma unroll
                for (int p = 0; p < 2; p++) {
                    float e0 = __expf(acc[mt][nt][2 * p + 0]);
                    float e1 = __expf(acc[mt][nt][2 * p + 1]);
                    acc[mt][nt][2 * p + 0] = e0;
                    acc[mt][nt][2 * p + 1] = e1;
                    rs[mt][p] += e0 + e1;
                }
#pragma unroll
        for (int mt = 0; mt < 2; mt++)
#pragma unroll
            for (int p = 0; p < 2; p++) {
                int row = m0 + wm * 32 + mt * 16 + g + 8 * p;
#pragma unroll
                for (int nt = 0; nt < 4; nt++) {
                    int col = n0 + wn * 32 + nt * 8 + 2 * t;
                    size_t e = (size_t)bz * SEQ * SEQ + atile(row, col, 128);
                    uint32_t hh, ll;
                    split2(acc[mt][nt][2 * p + 0], acc[mt][nt][2 * p + 1], hh, ll);
                    *(uint32_t*)(P.outH + e) = hh;
                    *(uint32_t*)(P.outL + e) = ll;
                }
                float s2 = rs[mt][p];
                s2 += __shfl_xor_sync(0xffffffffu, s2, 1);
                s2 += __shfl_xor_sync(0xffffffffu, s2, 2);
                if (t == 0) atomicAdd(&P.rowsum[bz * SEQ + row], s2);
            }
        return;
    }

#pragma unroll
    for (int mt = 0; mt < 2; mt++)
#pragma unroll
        for (int nt = 0; nt < 4; nt++)
#pragma unroll
            for (int p = 0; p < 2; p++) {
                int row = m0 + wm * 32 + mt * 16 + g + 8 * p;
                int col = n0 + wn * 32 + nt * 8 + 2 * t;
                float v0 = acc[mt][nt][2 * p + 0];
                float v1 = acc[mt][nt][2 * p + 1];
                if (mode == 0 || mode == 5) {
                    int b = row >> 11, sq = row & (SEQ - 1);
                    int h = col >> 6, hd = col & (HDIM - 1);
                    v0 = (v0 + P.bias[col]) * P.scale;
                    v1 = (v1 + P.bias[col + 1]) * P.scale;
                    uint32_t hh, ll;
                    split2(v0, v1, hh, ll);
                    size_t base = (size_t)(b * NH + h) * SEQ * HDIM;
                    size_t e = base + ((mode == 0) ? atile(sq, hd, 4) : btile(sq, hd, 4));
                    *(uint32_t*)(P.outH + e) = hh;
                    *(uint32_t*)(P.outL + e) = ll;
                } else if (mode == 1) {
                    int b = row >> 11, sq = row & (SEQ - 1);
                    v0 = v0 + P.bias[col];
                    v1 = v1 + P.bias[col + 1];
#pragma unroll
                    for (int e2 = 0; e2 < 2; e2++) {
                        int cc = col + e2;
                        float v = e2 ? v1 : v0;
                        int h = cc >> 6, hd = cc & (HDIM - 1);
                        __nv_bfloat16 hi = __float2bfloat16(v);
                        __nv_bfloat16 lo = __float2bfloat16(v - __bfloat162float(hi));
                        size_t e = (size_t)(b * NH + h) * HDIM * SEQ + btile(hd, sq, 128);
                        P.outH[e] = hi;
                        P.outL[e] = lo;
                    }
                } else if (mode == 2) {
                    *(float2*)(P.outF + (size_t)row * DIM + col)
                        = make_float2(v0 + P.bias[col], v1 + P.bias[col + 1]);
                } else {  // mode 4
                    float inv = 1.0f / P.rowsum[bz * SEQ + row];
                    v0 *= inv;
                    v1 *= inv;
                    int b = bz >> 4, h = bz & (NH - 1);
                    int gm = b * SEQ + row, gc = h * HDIM + col;
                    uint32_t hh, ll;
                    split2(v0, v1, hh, ll);
                    size_t e = atile(gm, gc, 64);
                    *(uint32_t*)(P.outH + e) = hh;
                    *(uint32_t*)(P.outL + e) = ll;
                }
            }
}

// ---------------- host ----------------
static void* sym(const void* s) { void* p; cudaGetSymbolAddress(&p, s); return p; }

extern "C" void kernel_launch(void* const* d_in, const int* in_sizes, int n_in,
                              void* d_out, int out_size)
{
    const float* x  = (const float*)d_in[0];
    const float* Wq = (const float*)d_in[1];
    const float* bq = (const float*)d_in[2];
    const float* Wk = (const float*)d_in[3];
    const float* bk = (const float*)d_in[4];
    const float* Wv = (const float*)d_in[5];
    const float* bv = (const float*)d_in[6];
    const float* Wo = (const float*)d_in[7];
    const float* bo = (const float*)d_in[8];
    float* out = (float*)d_out;

    constexpr int SMEM = 2 * 16384;   // 32768
    cudaFuncSetAttribute(gemm_kernel, cudaFuncAttributeMaxDynamicSharedMemorySize, SMEM);

    __nv_bfloat16 *xh = (__nv_bfloat16*)sym(g_xh), *xl = (__nv_bfloat16*)sym(g_xl);
    __nv_bfloat16 *wqh = (__nv_bfloat16*)sym(g_Wqh), *wql = (__nv_bfloat16*)sym(g_Wql);
    __nv_bfloat16 *wkh = (__nv_bfloat16*)sym(g_Wkh), *wkl = (__nv_bfloat16*)sym(g_Wkl);
    __nv_bfloat16 *wvh = (__nv_bfloat16*)sym(g_Wvh), *wvl = (__nv_bfloat16*)sym(g_Wvl);
    __nv_bfloat16 *woh = (__nv_bfloat16*)sym(g_Woh), *wol = (__nv_bfloat16*)sym(g_Wol);
    __nv_bfloat16 *qh = (__nv_bfloat16*)sym(g_Qh), *ql = (__nv_bfloat16*)sym(g_Ql);
    __nv_bfloat16 *kh = (__nv_bfloat16*)sym(g_Kh), *kl = (__nv_bfloat16*)sym(g_Kl);
    __nv_bfloat16 *vth = (__nv_bfloat16*)sym(g_Vth), *vtl = (__nv_bfloat16*)sym(g_Vtl);
    __nv_bfloat16 *pwh = (__nv_bfloat16*)sym(g_Ph), *pwl = (__nv_bfloat16*)sym(g_Pl);
    __nv_bfloat16 *ah = (__nv_bfloat16*)sym(g_Ah), *al = (__nv_bfloat16*)sym(g_Al);
    float* rsum = (float*)sym(g_rowsum);

    cudaMemsetAsync(rsum, 0, BH * SEQ * sizeof(float), 0);

    splitx_kernel<<<2048, 256>>>(x);   // 16384 tiles * 32 lanes / 256

    WS ws;
    ws.W[0] = Wq;  ws.th[0] = wqh;  ws.tl[0] = wql;
    ws.W[1] = Wk;  ws.th[1] = wkh;  ws.tl[1] = wkl;
    ws.W[2] = Wv;  ws.th[2] = wvh;  ws.tl[2] = wvl;
    ws.W[3] = Wo;  ws.th[3] = woh;  ws.tl[3] = wol;
    wsplit4_kernel<<<dim3(512, 1, 4), 256>>>(ws);

    dim3 blk(128);
    dim3 gproj(DIM / 64, MROWS / 64, 1);

    GP q  = {xh, xl, wqh, wql, 0, 0, bq, 0.125f, DIM, 0, qh, ql, nullptr, nullptr};
    GP k  = {xh, xl, wkh, wkl, 0, 0, bk, 1.0f,   DIM, 5, kh, kl, nullptr, nullptr};
    GP v  = {xh, xl, wvh, wvl, 0, 0, bv, 1.0f,   DIM, 1, vth, vtl, nullptr, nullptr};
    GP s  = {qh, ql, kh, kl, (long)SEQ * HDIM, (long)SEQ * HDIM,
             nullptr, 1.0f, HDIM, 3, pwh, pwl, nullptr, rsum};
    GP av = {pwh, pwl, vth, vtl, (long)SEQ * SEQ, (long)HDIM * SEQ,
             nullptr, 1.0f, SEQ, 4, ah, al, nullptr, rsum};
    GP o  = {ah, al, woh, wol, 0, 0, bo, 1.0f, DIM, 2, nullptr, nullptr, out, nullptr};

    gemm_kernel<<<gproj, blk, SMEM>>>(q);
    gemm_kernel<<<gproj, blk, SMEM>>>(k);
    gemm_kernel<<<gproj, blk, SMEM>>>(v);
    gemm_kernel<<<dim3(SEQ / 64, SEQ / 64, BH), blk, SMEM>>>(s);
    gemm_kernel<<<dim3(1, SEQ / 64, BH), blk, SMEM>>>(av);
    gemm_kernel<<<gproj, blk, SMEM>>>(o);
}

// round 15
// speedup vs baseline: 1.5719x; 1.1590x over previous
#include <cuda_runtime.h>
#include <cuda_fp16.h>
#include <math.h>
#include <stdint.h>

#define BH    32
#define SEQ   2048
#define DIM   1024
#define NH    16
#define HDIM  64
#define MROWS 4096

// ---------------- device scratch (fragment-tiled, 16B aligned) ----------------
__device__ __align__(16) __half g_xh[MROWS * DIM], g_xl[MROWS * DIM];       // A-tiled
__device__ __align__(16) __half g_Wq1[DIM * DIM], g_Wk1[DIM * DIM];         // B-tiled x32
__device__ __align__(16) __half g_Wv1[DIM * DIM], g_Wo1[DIM * DIM];
__device__ __align__(16) __half g_Qh[BH * SEQ * HDIM], g_Ql[BH * SEQ * HDIM];  // A-tiled
__device__ __align__(16) __half g_K1[BH * SEQ * HDIM];                         // B-tiled
__device__ __align__(16) __half g_Vt1[BH * HDIM * SEQ];                        // B-tiled (hd-major)
__device__ __align__(16) __half g_Ph[(size_t)BH * SEQ * SEQ], g_Pl[(size_t)BH * SEQ * SEQ];
__device__ float g_rowsum[BH * SEQ];
__device__ __align__(16) __half g_Ah[(size_t)MROWS * DIM], g_Al[(size_t)MROWS * DIM]; // x4

// ---------------- helpers ----------------
__device__ __forceinline__ uint32_t smem_u32(const void* p) {
    uint32_t a;
    asm("{ .reg .u64 t; cvta.to.shared.u64 t, %1; cvt.u32.u64 %0, t; }" : "=r"(a) : "l"(p));
    return a;
}
__device__ __forceinline__ void cp16(uint32_t s, const void* g) {
    asm volatile("cp.async.cg.shared.global [%0], [%1], 16;" :: "r"(s), "l"(g));
}
__device__ __forceinline__ void mma_f16(float* d, const uint32_t* a, const uint32_t* b) {
    asm volatile(
        "mma.sync.aligned.m16n8k16.row.col.f32.f16.f16.f32 "
        "{%0,%1,%2,%3}, {%4,%5,%6,%7}, {%8,%9}, {%0,%1,%2,%3};"
        : "+f"(d[0]), "+f"(d[1]), "+f"(d[2]), "+f"(d[3])
        : "r"(a[0]), "r"(a[1]), "r"(a[2]), "r"(a[3]), "r"(b[0]), "r"(b[1]));
}
#define LDS128(r, addr) \
    asm volatile("ld.shared.v4.b32 {%0,%1,%2,%3}, [%4];" \
        : "=r"((r)[0]), "=r"((r)[1]), "=r"((r)[2]), "=r"((r)[3]) : "r"(addr))

__device__ __forceinline__ uint32_t pack2(float v0, float v1) {
    __half h0 = __float2half_rn(v0), h1 = __float2half_rn(v1);
    return ((uint32_t)__half_as_ushort(h1) << 16) | __half_as_ushort(h0);
}
__device__ __forceinline__ void split2(float v0, float v1, uint32_t& h, uint32_t& l) {
    __half h0 = __float2half_rn(v0), h1 = __float2half_rn(v1);
    h = ((uint32_t)__half_as_ushort(h1) << 16) | __half_as_ushort(h0);
    __half l0 = __float2half_rn(v0 - __half2float(h0));
    __half l1 = __float2half_rn(v1 - __half2float(h1));
    l = ((uint32_t)__half_as_ushort(l1) << 16) | __half_as_ushort(l0);
}

// fragment-tiled index maps
__device__ __forceinline__ size_t atile(int m, int k, int ktiles) {
    int r = m & 15, c = k & 15;
    return ((((size_t)(m >> 4)) * ktiles + (k >> 4)) << 8)
         + ((((r & 7) << 2) + ((c & 7) >> 1)) << 3)
         + (((r >> 3) + ((c >> 3) << 1)) << 1) + (c & 1);
}
__device__ __forceinline__ size_t btile(int n, int k, int ktiles) {
    int nn = n & 15, kk = k & 15;
    return ((((size_t)(n >> 4)) * ktiles + (k >> 4)) << 8)
         + ((((nn & 7) << 2) + ((kk & 7) >> 1)) << 3)
         + (((kk >> 3) + ((nn >> 3) << 1)) << 1) + (kk & 1);
}

// ---------------- GEMM parameter block ----------------
struct GP {
    const __half *Ah, *Al, *B;
    long bStrideA, bStrideB;
    const float* bias;
    float cs;          // dequant multiplier (applied to raw accum)
    float scale;       // extra out multiplier (storage scale)
    int Ktot, mode;
    __half *outH, *outL;
    float *outF, *rowsum;
};

// ---------------- conversion kernels ----------------
// x [MROWS, DIM] fp32 -> A-tiled fp16 hi/lo
__global__ __launch_bounds__(256) void splitx_kernel(const float* __restrict__ x) {
    int slot = blockIdx.x * 256 + threadIdx.x;
    int tile = slot >> 5, lane = slot & 31;
    int tm = tile >> 6, tk = tile & 63;
    int rg = lane >> 2, tq = lane & 3;
    const float* b0 = x + (size_t)(tm * 16 + rg) * DIM + tk * 16 + tq * 2;
    float2 f00 = *(const float2*)b0;
    float2 f10 = *(const float2*)(b0 + 8 * DIM);
    float2 f01 = *(const float2*)(b0 + 8);
    float2 f11 = *(const float2*)(b0 + 8 * DIM + 8);
    uint4 hv, lv;
    split2(f00.x, f00.y, hv.x, lv.x);
    split2(f10.x, f10.y, hv.y, lv.y);
    split2(f01.x, f01.y, hv.z, lv.z);
    split2(f11.x, f11.y, hv.w, lv.w);
    ((uint4*)g_xh)[slot] = hv;
    ((uint4*)g_xl)[slot] = lv;
}

// W [DIM(k), DIM(n)] -> B-tiled W^T x32, single fp16
struct WS { const float* W[4]; __half* t1[4]; };
__global__ __launch_bounds__(256) void wsplit4_kernel(WS ws) {
    int slot = blockIdx.x * 256 + threadIdx.x;
    int tile = slot >> 5, lane = slot & 31;
    int tn = tile >> 6, tk = tile & 63;
    int g = lane >> 2, tq = lane & 3;
    const float* W = ws.W[blockIdx.z];
    const float* c0 = W + (size_t)(tk * 16 + tq * 2) * DIM + tn * 16 + g;
    uint4 hv;
    hv.x = pack2(c0[0] * 32.f,           c0[DIM] * 32.f);
    hv.y = pack2(c0[8 * DIM] * 32.f,     c0[9 * DIM] * 32.f);
    hv.z = pack2(c0[8] * 32.f,           c0[DIM + 8] * 32.f);
    hv.w = pack2(c0[8 * DIM + 8] * 32.f, c0[9 * DIM + 8] * 32.f);
    ((uint4*)ws.t1[blockIdx.z])[slot] = hv;
}

// ---------------- GEMM: CTA 64x64, 4 warps, A hi/lo fp16 + B single fp16, 2 terms -
// modes: 0 Q (A-tiled hi/lo), 5 K (B-tiled single), 1 Vt (B-tiled single, transposed),
//        2 fp32 out (+bias), 3 exp->P (A-tiled hi/lo) + rowsum, 4 attn (A-tiled hi/lo)
__global__ __launch_bounds__(128, 5) void gemm_kernel(GP P)
{
    extern __shared__ char smem[];
    constexpr int STAGE = 12288;   // Ahi 4K | Alo 4K | B 4K

    const int tid = threadIdx.x;
    const int w = tid >> 5, lane = tid & 31;
    const int g = lane >> 2, t = lane & 3;
    const int wm = w & 1, wn = w >> 1;
    const int bx = blockIdx.x, by = blockIdx.y, bz = blockIdx.z;
    const __half* Ah = P.Ah + (size_t)bz * P.bStrideA;
    const __half* Al = P.Al + (size_t)bz * P.bStrideA;
    const __half* Bp = P.B + (size_t)bz * P.bStrideB;

    const int m0 = by * 64, n0 = bx * 64;
    const int ktiles = P.Ktot >> 4;
    const int nch = P.Ktot >> 5;
    const uint32_t sb = smem_u32(smem);

    float acc[2][4][4];
#pragma unroll
    for (int i = 0; i < 2; i++)
#pragma unroll
        for (int j = 0; j < 4; j++)
#pragma unroll
            for (int k = 0; k < 4; k++) acc[i][j][k] = 0.f;

    auto stage_load = [&](int buf, int c) {
        const uint32_t so = sb + buf * STAGE;
        const int kt = c << 1;
#pragma unroll
        for (int i = tid; i < 512; i += 128) {      // A: hi,lo planes x 8 tiles
            int pl = i >> 8, seg = i & 255, tl2 = seg >> 5, s = seg & 31;
            size_t go = (((size_t)((m0 >> 4) + (tl2 >> 1))) * ktiles + kt + (tl2 & 1)) * 256
                      + s * 8;
            cp16(so + pl * 4096 + tl2 * 512 + s * 16, (pl ? Al : Ah) + go);
        }
#pragma unroll
        for (int i = tid; i < 256; i += 128) {      // B: single plane x 8 tiles
            int tl2 = i >> 5, s = i & 31;
            size_t go = (((size_t)((n0 >> 4) + (tl2 >> 1))) * ktiles + kt + (tl2 & 1)) * 256
                      + s * 8;
            cp16(so + 8192 + tl2 * 512 + s * 16, Bp + go);
        }
        asm volatile("cp.async.commit_group;");
    };

    stage_load(0, 0);
    for (int c = 0; c < nch; c++) {
        const int buf = c & 1;
        if (c + 1 < nch) {
            stage_load(buf ^ 1, c + 1);
            asm volatile("cp.async.wait_group 1;");
        } else {
            asm volatile("cp.async.wait_group 0;");
        }
        __syncthreads();

        const uint32_t so = sb + buf * STAGE;
#pragma unroll
        for (int ks = 0; ks < 2; ks++) {
            uint32_t ah[2][4], al[2][4], b4[2][4];
#pragma unroll
            for (int mt = 0; mt < 2; mt++) {
                uint32_t a = so + ((((wm * 2 + mt) << 1) + ks) << 9) + (lane << 4);
                LDS128(ah[mt], a);
                LDS128(al[mt], a + 4096);
            }
#pragma unroll
            for (int p2 = 0; p2 < 2; p2++) {
                uint32_t b = so + 8192 + ((((wn * 2 + p2) << 1) + ks) << 9) + (lane << 4);
                LDS128(b4[p2], b);
            }
#pragma unroll
            for (int mt = 0; mt < 2; mt++)
#pragma unroll
                for (int nt = 0; nt < 4; nt++)
                    mma_f16(acc[mt][nt], ah[mt], &b4[nt >> 1][(nt & 1) << 1]);
#pragma unroll
            for (int mt = 0; mt < 2; mt++)
#pragma unroll
                for (int nt = 0; nt < 4; nt++)
                    mma_f16(acc[mt][nt], al[mt], &b4[nt >> 1][(nt & 1) << 1]);
        }
        __syncthreads();
    }

    // ---------------- epilogue ----------------
    const int mode = P.mode;
    if (mode == 3) {
        float rs[2][2] = {};
#pragma unroll
        for (int mt = 0; mt < 2; mt++)
#pragma unroll
            for (int nt = 0; nt < 4; nt++)
#pragma unroll
                for (int p = 0; p < 2; p++) {
                    float e0 = __expf(acc[mt][nt][2 * p + 0] * P.cs);
                    float e1 = __expf(acc[mt][nt][2 * p + 1] * P.cs);
                    acc[mt][nt][2 * p + 0] = e0;
                    acc[mt][nt][2 * p + 1] = e1;
                    rs[mt][p] += e0 + e1;
                }
#pragma unroll
        for (int mt = 0; mt < 2; mt++)
#pragma unroll
            for (int p = 0; p < 2; p++) {
                int row = m0 + wm * 32 + mt * 16 + g + 8 * p;
#pragma unroll
                for (int nt = 0; nt < 4; nt++) {
                    int col = n0 + wn * 32 + nt * 8 + 2 * t;
                    size_t e = (size_t)bz * SEQ * SEQ + atile(row, col, 128);
                    uint32_t hh, ll;
                    split2(acc[mt][nt][2 * p + 0], acc[mt][nt][2 * p + 1], hh, ll);
                    *(uint32_t*)(P.outH + e) = hh;
                    *(uint32_t*)(P.outL + e) = ll;
                }
                float s2 = rs[mt][p];
                s2 += __shfl_xor_sync(0xffffffffu, s2, 1);
                s2 += __shfl_xor_sync(0xffffffffu, s2, 2);
                if (t == 0) atomicAdd(&P.rowsum[bz * SEQ + row], s2);
            }
        return;
    }

#pragma unroll
    for (int mt = 0; mt < 2; mt++)
#pragma unroll
        for (int nt = 0; nt < 4; nt++)
#pragma unroll
            for (int p = 0; p < 2; p++) {
                int row = m0 + wm * 32 + mt * 16 + g + 8 * p;
                int col = n0 + wn * 32 + nt * 8 + 2 * t;
                float v0 = acc[mt][nt][2 * p + 0];
                float v1 = acc[mt][nt][2 * p + 1];
                if (mode == 0) {          // Q: hi/lo A-tiled head-split
                    int b = row >> 11, sq = row & (SEQ - 1);
                    int h = col >> 6, hd = col & (HDIM - 1);
                    v0 = v0 * P.cs + P.bias[col];
                    v1 = v1 * P.cs + P.bias[col + 1];
                    uint32_t hh, ll;
                    split2(v0, v1, hh, ll);
                    size_t e = (size_t)(b * NH + h) * SEQ * HDIM + atile(sq, hd, 4);
                    *(uint32_t*)(P.outH + e) = hh;
                    *(uint32_t*)(P.outL + e) = ll;
                } else if (mode == 5) {   // K: single B-tiled head-split
                    int b = row >> 11, sq = row & (SEQ - 1);
                    int h = col >> 6, hd = col & (HDIM - 1);
                    v0 = v0 * P.cs + P.bias[col];
                    v1 = v1 * P.cs + P.bias[col + 1];
                    size_t e = (size_t)(b * NH + h) * SEQ * HDIM + btile(sq, hd, 4);
                    *(uint32_t*)(P.outH + e) = pack2(v0, v1);
                } else if (mode == 1) {   // Vt: single B-tiled transposed
                    int b = row >> 11, sq = row & (SEQ - 1);
                    v0 = v0 * P.cs + P.bias[col];
                    v1 = v1 * P.cs + P.bias[col + 1];
#pragma unroll
                    for (int e2 = 0; e2 < 2; e2++) {
                        int cc = col + e2;
                        int h = cc >> 6, hd = cc & (HDIM - 1);
                        size_t e = (size_t)(b * NH + h) * HDIM * SEQ + btile(hd, sq, 128);
                        P.outH[e] = __float2half_rn(e2 ? v1 : v0);
                    }
                } else if (mode == 2) {   // fp32 out + bias
                    *(float2*)(P.outF + (size_t)row * DIM + col)
                        = make_float2(v0 * P.cs + P.bias[col], v1 * P.cs + P.bias[col + 1]);
                } else {                  // mode 4: attn hi/lo A-tiled, x4 storage scale
                    float inv = P.scale / P.rowsum[bz * SEQ + row];
                    v0 *= inv;
                    v1 *= inv;
                    int b = bz >> 4, h = bz & (NH - 1);
                    int gm = b * SEQ + row, gc = h * HDIM + col;
                    uint32_t hh, ll;
                    split2(v0, v1, hh, ll);
                    size_t e = atile(gm, gc, 64);
                    *(uint32_t*)(P.outH + e) = hh;
                    *(uint32_t*)(P.outL + e) = ll;
                }
            }
}

// ---------------- host ----------------
static void* sym(const void* s) { void* p; cudaGetSymbolAddress(&p, s); return p; }

extern "C" void kernel_launch(void* const* d_in, const int* in_sizes, int n_in,
                              void* d_out, int out_size)
{
    const float* x  = (const float*)d_in[0];
    const float* Wq = (const float*)d_in[1];
    const float* bq = (const float*)d_in[2];
    const float* Wk = (const float*)d_in[3];
    const float* bk = (const float*)d_in[4];
    const float* Wv = (const float*)d_in[5];
    const float* bv = (const float*)d_in[6];
    const float* Wo = (const float*)d_in[7];
    const float* bo = (const float*)d_in[8];
    float* out = (float*)d_out;

    constexpr int SMEM = 2 * 12288;   // 24576
    cudaFuncSetAttribute(gemm_kernel, cudaFuncAttributeMaxDynamicSharedMemorySize, SMEM);

    __half *xh = (__half*)sym(g_xh), *xl = (__half*)sym(g_xl);
    __half *wq1 = (__half*)sym(g_Wq1), *wk1 = (__half*)sym(g_Wk1);
    __half *wv1 = (__half*)sym(g_Wv1), *wo1 = (__half*)sym(g_Wo1);
    __half *qh = (__half*)sym(g_Qh), *ql = (__half*)sym(g_Ql);
    __half *k1 = (__half*)sym(g_K1), *vt1 = (__half*)sym(g_Vt1);
    __half *pwh = (__half*)sym(g_Ph), *pwl = (__half*)sym(g_Pl);
    __half *ah = (__half*)sym(g_Ah), *al = (__half*)sym(g_Al);
    float* rsum = (float*)sym(g_rowsum);

    cudaMemsetAsync(rsum, 0, BH * SEQ * sizeof(float), 0);

    splitx_kernel<<<2048, 256>>>(x);

    WS ws;
    ws.W[0] = Wq;  ws.t1[0] = wq1;
    ws.W[1] = Wk;  ws.t1[1] = wk1;
    ws.W[2] = Wv;  ws.t1[2] = wv1;
    ws.W[3] = Wo;  ws.t1[3] = wo1;
    wsplit4_kernel<<<dim3(512, 1, 4), 256>>>(ws);

    dim3 blk(128);
    dim3 gproj(DIM / 64, MROWS / 64, 1);

    // cs = csA*csB: x plain, W stored x32 -> 1/32. attn stored x4 -> out-proj 1/128.
    GP q  = {xh, xl, wq1, 0, 0, bq, 1.f / 32.f, 1.f, DIM, 0, qh, ql, nullptr, nullptr};
    GP k  = {xh, xl, wk1, 0, 0, bk, 1.f / 32.f, 1.f, DIM, 5, k1, nullptr, nullptr, nullptr};
    GP v  = {xh, xl, wv1, 0, 0, bv, 1.f / 32.f, 1.f, DIM, 1, vt1, nullptr, nullptr, nullptr};
    GP s  = {qh, ql, k1, (long)SEQ * HDIM, (long)SEQ * HDIM,
             nullptr, 0.125f, 1.f, HDIM, 3, pwh, pwl, nullptr, rsum};
    GP av = {pwh, pwl, vt1, (long)SEQ * SEQ, (long)HDIM * SEQ,
             nullptr, 1.f, 4.f, SEQ, 4, ah, al, nullptr, rsum};
    GP o  = {ah, al, wo1, 0, 0, bo, 1.f / 128.f, 1.f, DIM, 2, nullptr, nullptr, out, nullptr};

    gemm_kernel<<<gproj, blk, SMEM>>>(q);
    gemm_kernel<<<gproj, blk, SMEM>>>(k);
    gemm_kernel<<<gproj, blk, SMEM>>>(v);
    gemm_kernel<<<dim3(SEQ / 64, SEQ / 64, BH), blk, SMEM>>>(s);
    gemm_kernel<<<dim3(1, SEQ / 64, BH), blk, SMEM>>>(av);
    gemm_kernel<<<gproj, blk, SMEM>>>(o);
}

// round 16
// speedup vs baseline: 2.5865x; 1.6454x over previous
#include <cuda_runtime.h>
#include <cuda_fp16.h>
#include <math.h>
#include <stdint.h>

#define BH    32
#define SEQ   2048
#define DIM   1024
#define NH    16
#define HDIM  64
#define MROWS 4096

// ---------------- device scratch (fragment-tiled, single fp16) ----------------
__device__ __align__(16) __half g_x1[MROWS * DIM];                     // A-tiled
__device__ __align__(16) __half g_Wq1[DIM * DIM], g_Wk1[DIM * DIM];    // B-tiled x32
__device__ __align__(16) __half g_Wv1[DIM * DIM], g_Wo1[DIM * DIM];
__device__ __align__(16) __half g_Q1[BH * SEQ * HDIM];                 // A-tiled
__device__ __align__(16) __half g_K1[BH * SEQ * HDIM];                 // B-tiled
__device__ __align__(16) __half g_Vt1[BH * HDIM * SEQ];                // B-tiled (hd-major)
__device__ __align__(16) __half g_P1[(size_t)BH * SEQ * SEQ];          // A-tiled
__device__ float g_rowsum[BH * SEQ];
__device__ __align__(16) __half g_A1[MROWS * DIM];                     // A-tiled x4

// ---------------- helpers ----------------
__device__ __forceinline__ uint32_t smem_u32(const void* p) {
    uint32_t a;
    asm("{ .reg .u64 t; cvta.to.shared.u64 t, %1; cvt.u32.u64 %0, t; }" : "=r"(a) : "l"(p));
    return a;
}
__device__ __forceinline__ void cp16(uint32_t s, const void* g) {
    asm volatile("cp.async.cg.shared.global [%0], [%1], 16;" :: "r"(s), "l"(g));
}
__device__ __forceinline__ void mma_f16(float* d, const uint32_t* a, const uint32_t* b) {
    asm volatile(
        "mma.sync.aligned.m16n8k16.row.col.f32.f16.f16.f32 "
        "{%0,%1,%2,%3}, {%4,%5,%6,%7}, {%8,%9}, {%0,%1,%2,%3};"
        : "+f"(d[0]), "+f"(d[1]), "+f"(d[2]), "+f"(d[3])
        : "r"(a[0]), "r"(a[1]), "r"(a[2]), "r"(a[3]), "r"(b[0]), "r"(b[1]));
}
#define LDS128(r, addr) \
    asm volatile("ld.shared.v4.b32 {%0,%1,%2,%3}, [%4];" \
        : "=r"((r)[0]), "=r"((r)[1]), "=r"((r)[2]), "=r"((r)[3]) : "r"(addr))

__device__ __forceinline__ uint32_t pack2(float v0, float v1) {
    __half h0 = __float2half_rn(v0), h1 = __float2half_rn(v1);
    return ((uint32_t)__half_as_ushort(h1) << 16) | __half_as_ushort(h0);
}

// fragment-tiled index maps
__device__ __forceinline__ size_t atile(int m, int k, int ktiles) {
    int r = m & 15, c = k & 15;
    return ((((size_t)(m >> 4)) * ktiles + (k >> 4)) << 8)
         + ((((r & 7) << 2) + ((c & 7) >> 1)) << 3)
         + (((r >> 3) + ((c >> 3) << 1)) << 1) + (c & 1);
}
__device__ __forceinline__ size_t btile(int n, int k, int ktiles) {
    int nn = n & 15, kk = k & 15;
    return ((((size_t)(n >> 4)) * ktiles + (k >> 4)) << 8)
         + ((((nn & 7) << 2) + ((kk & 7) >> 1)) << 3)
         + (((kk >> 3) + ((nn >> 3) << 1)) << 1) + (kk & 1);
}

// ---------------- GEMM parameter block ----------------
struct GP {
    const __half *A, *B;
    long bStrideA, bStrideB;
    const float* bias;
    float cs;          // dequant multiplier on raw accum
    float scale;       // extra out multiplier (storage scale)
    int Ktot, mode;
    __half *outp;
    float *outF, *rowsum;
};

// ---------------- conversion kernels ----------------
// x [MROWS, DIM] fp32 -> A-tiled fp16
__global__ __launch_bounds__(256) void quantx_kernel(const float* __restrict__ x) {
    int slot = blockIdx.x * 256 + threadIdx.x;
    int tile = slot >> 5, lane = slot & 31;
    int tm = tile >> 6, tk = tile & 63;
    int rg = lane >> 2, tq = lane & 3;
    const float* b0 = x + (size_t)(tm * 16 + rg) * DIM + tk * 16 + tq * 2;
    float2 f00 = *(const float2*)b0;
    float2 f10 = *(const float2*)(b0 + 8 * DIM);
    float2 f01 = *(const float2*)(b0 + 8);
    float2 f11 = *(const float2*)(b0 + 8 * DIM + 8);
    uint4 hv;
    hv.x = pack2(f00.x, f00.y);
    hv.y = pack2(f10.x, f10.y);
    hv.z = pack2(f01.x, f01.y);
    hv.w = pack2(f11.x, f11.y);
    ((uint4*)g_x1)[slot] = hv;
}

// W [DIM(k), DIM(n)] -> B-tiled W^T x32
struct WS { const float* W[4]; __half* t1[4]; };
__global__ __launch_bounds__(256) void wsplit4_kernel(WS ws) {
    int slot = blockIdx.x * 256 + threadIdx.x;
    int tile = slot >> 5, lane = slot & 31;
    int tn = tile >> 6, tk = tile & 63;
    int g = lane >> 2, tq = lane & 3;
    const float* W = ws.W[blockIdx.z];
    const float* c0 = W + (size_t)(tk * 16 + tq * 2) * DIM + tn * 16 + g;
    uint4 hv;
    hv.x = pack2(c0[0] * 32.f,           c0[DIM] * 32.f);
    hv.y = pack2(c0[8 * DIM] * 32.f,     c0[9 * DIM] * 32.f);
    hv.z = pack2(c0[8] * 32.f,           c0[DIM + 8] * 32.f);
    hv.w = pack2(c0[8 * DIM + 8] * 32.f, c0[9 * DIM + 8] * 32.f);
    ((uint4*)ws.t1[blockIdx.z])[slot] = hv;
}

// ---------------- GEMM: CTA 64x64, 4 warps, single fp16, 1 term ----------------
// modes: 0 Q (A-tiled), 5 K (B-tiled), 1 Vt (B-tiled transposed),
//        2 fp32 out (+bias), 3 exp->P (A-tiled) + rowsum, 4 attn (A-tiled, x scale)
__global__ __launch_bounds__(128, 6) void gemm_kernel(GP P)
{
    extern __shared__ char smem[];
    constexpr int STAGE = 8192;   // A 4K | B 4K

    const int tid = threadIdx.x;
    const int w = tid >> 5, lane = tid & 31;
    const int g = lane >> 2, t = lane & 3;
    const int wm = w & 1, wn = w >> 1;
    const int bx = blockIdx.x, by = blockIdx.y, bz = blockIdx.z;
    const __half* Ap = P.A + (size_t)bz * P.bStrideA;
    const __half* Bp = P.B + (size_t)bz * P.bStrideB;

    const int m0 = by * 64, n0 = bx * 64;
    const int ktiles = P.Ktot >> 4;
    const int nch = P.Ktot >> 5;
    const uint32_t sb = smem_u32(smem);

    float acc[2][4][4];
#pragma unroll
    for (int i = 0; i < 2; i++)
#pragma unroll
        for (int j = 0; j < 4; j++)
#pragma unroll
            for (int k = 0; k < 4; k++) acc[i][j][k] = 0.f;

    auto stage_load = [&](int buf, int c) {
        const uint32_t so = sb + buf * STAGE;
        const int kt = c << 1;
#pragma unroll
        for (int i = tid; i < 256; i += 128) {      // A: 8 tiles x 512B
            int tl2 = i >> 5, s = i & 31;
            size_t go = (((size_t)((m0 >> 4) + (tl2 >> 1))) * ktiles + kt + (tl2 & 1)) * 256
                      + s * 8;
            cp16(so + tl2 * 512 + s * 16, Ap + go);
        }
#pragma unroll
        for (int i = tid; i < 256; i += 128) {      // B: 8 tiles x 512B
            int tl2 = i >> 5, s = i & 31;
            size_t go = (((size_t)((n0 >> 4) + (tl2 >> 1))) * ktiles + kt + (tl2 & 1)) * 256
                      + s * 8;
            cp16(so + 4096 + tl2 * 512 + s * 16, Bp + go);
        }
        asm volatile("cp.async.commit_group;");
    };

    stage_load(0, 0);
    for (int c = 0; c < nch; c++) {
        const int buf = c & 1;
        if (c + 1 < nch) {
            stage_load(buf ^ 1, c + 1);
            asm volatile("cp.async.wait_group 1;");
        } else {
            asm volatile("cp.async.wait_group 0;");
        }
        __syncthreads();

        const uint32_t so = sb + buf * STAGE;
#pragma unroll
        for (int ks = 0; ks < 2; ks++) {
            uint32_t a4[2][4], b4[2][4];
#pragma unroll
            for (int mt = 0; mt < 2; mt++) {
                uint32_t a = so + ((((wm * 2 + mt) << 1) + ks) << 9) + (lane << 4);
                LDS128(a4[mt], a);
            }
#pragma unroll
            for (int p2 = 0; p2 < 2; p2++) {
                uint32_t b = so + 4096 + ((((wn * 2 + p2) << 1) + ks) << 9) + (lane << 4);
                LDS128(b4[p2], b);
            }
#pragma unroll
            for (int mt = 0; mt < 2; mt++)
#pragma unroll
                for (int nt = 0; nt < 4; nt++)
                    mma_f16(acc[mt][nt], a4[mt], &b4[nt >> 1][(nt & 1) << 1]);
        }
        __syncthreads();
    }

    // ---------------- epilogue ----------------
    const int mode = P.mode;
    if (mode == 3) {
        float rs[2][2] = {};
#pragma unroll
        for (int mt = 0; mt < 2; mt++)
#pragma unroll
            for (int nt = 0; nt < 4; nt++)
#pragma unroll
                for (int p = 0; p < 2; p++) {
                    float e0 = __expf(acc[mt][nt][2 * p + 0] * P.cs);
                    float e1 = __expf(acc[mt][nt][2 * p + 1] * P.cs);
                    acc[mt][nt][2 * p + 0] = e0;
                    acc[mt][nt][2 * p + 1] = e1;
                    rs[mt][p] += e0 + e1;
                }
#pragma unroll
        for (int mt = 0; mt < 2; mt++)
#pragma unroll
            for (int p = 0; p < 2; p++) {
                int row = m0 + wm * 32 + mt * 16 + g + 8 * p;
#pragma unroll
                for (int nt = 0; nt < 4; nt++) {
                    int col = n0 + wn * 32 + nt * 8 + 2 * t;
                    size_t e = (size_t)bz * SEQ * SEQ + atile(row, col, 128);
                    *(uint32_t*)(P.outp + e)
                        = pack2(acc[mt][nt][2 * p + 0], acc[mt][nt][2 * p + 1]);
                }
                float s2 = rs[mt][p];
                s2 += __shfl_xor_sync(0xffffffffu, s2, 1);
                s2 += __shfl_xor_sync(0xffffffffu, s2, 2);
                if (t == 0) atomicAdd(&P.rowsum[bz * SEQ + row], s2);
            }
        return;
    }

#pragma unroll
    for (int mt = 0; mt < 2; mt++)
#pragma unroll
        for (int nt = 0; nt < 4; nt++)
#pragma unroll
            for (int p = 0; p < 2; p++) {
                int row = m0 + wm * 32 + mt * 16 + g + 8 * p;
                int col = n0 + wn * 32 + nt * 8 + 2 * t;
                float v0 = acc[mt][nt][2 * p + 0];
                float v1 = acc[mt][nt][2 * p + 1];
                if (mode == 0) {          // Q: A-tiled head-split
                    int b = row >> 11, sq = row & (SEQ - 1);
                    int h = col >> 6, hd = col & (HDIM - 1);
                    v0 = v0 * P.cs + P.bias[col];
                    v1 = v1 * P.cs + P.bias[col + 1];
                    size_t e = (size_t)(b * NH + h) * SEQ * HDIM + atile(sq, hd, 4);
                    *(uint32_t*)(P.outp + e) = pack2(v0, v1);
                } else if (mode == 5) {   // K: B-tiled head-split
                    int b = row >> 11, sq = row & (SEQ - 1);
                    int h = col >> 6, hd = col & (HDIM - 1);
                    v0 = v0 * P.cs + P.bias[col];
                    v1 = v1 * P.cs + P.bias[col + 1];
                    size_t e = (size_t)(b * NH + h) * SEQ * HDIM + btile(sq, hd, 4);
                    *(uint32_t*)(P.outp + e) = pack2(v0, v1);
                } else if (mode == 1) {   // Vt: B-tiled transposed
                    int b = row >> 11, sq = row & (SEQ - 1);
                    v0 = v0 * P.cs + P.bias[col];
                    v1 = v1 * P.cs + P.bias[col + 1];
#pragma unroll
                    for (int e2 = 0; e2 < 2; e2++) {
                        int cc = col + e2;
                        int h = cc >> 6, hd = cc & (HDIM - 1);
                        size_t e = (size_t)(b * NH + h) * HDIM * SEQ + btile(hd, sq, 128);
                        P.outp[e] = __float2half_rn(e2 ? v1 : v0);
                    }
                } else if (mode == 2) {   // fp32 out + bias
                    *(float2*)(P.outF + (size_t)row * DIM + col)
                        = make_float2(v0 * P.cs + P.bias[col], v1 * P.cs + P.bias[col + 1]);
                } else {                  // mode 4: attn A-tiled, x4 storage scale
                    float inv = P.scale / P.rowsum[bz * SEQ + row];
                    v0 *= inv;
                    v1 *= inv;
                    int b = bz >> 4, h = bz & (NH - 1);
                    int gm = b * SEQ + row, gc = h * HDIM + col;
                    size_t e = atile(gm, gc, 64);
                    *(uint32_t*)(P.outp + e) = pack2(v0, v1);
                }
            }
}

// ---------------- host ----------------
static void* sym(const void* s) { void* p; cudaGetSymbolAddress(&p, s); return p; }

extern "C" void kernel_launch(void* const* d_in, const int* in_sizes, int n_in,
                              void* d_out, int out_size)
{
    const float* x  = (const float*)d_in[0];
    const float* Wq = (const float*)d_in[1];
    const float* bq = (const float*)d_in[2];
    const float* Wk = (const float*)d_in[3];
    const float* bk = (const float*)d_in[4];
    const float* Wv = (const float*)d_in[5];
    const float* bv = (const float*)d_in[6];
    const float* Wo = (const float*)d_in[7];
    const float* bo = (const float*)d_in[8];
    float* out = (float*)d_out;

    constexpr int SMEM = 2 * 8192;   // 16384
    cudaFuncSetAttribute(gemm_kernel, cudaFuncAttributeMaxDynamicSharedMemorySize, SMEM);

    __half *x1 = (__half*)sym(g_x1);
    __half *wq1 = (__half*)sym(g_Wq1), *wk1 = (__half*)sym(g_Wk1);
    __half *wv1 = (__half*)sym(g_Wv1), *wo1 = (__half*)sym(g_Wo1);
    __half *q1 = (__half*)sym(g_Q1), *k1 = (__half*)sym(g_K1), *vt1 = (__half*)sym(g_Vt1);
    __half *p1 = (__half*)sym(g_P1), *a1 = (__half*)sym(g_A1);
    float* rsum = (float*)sym(g_rowsum);

    cudaMemsetAsync(rsum, 0, BH * SEQ * sizeof(float), 0);

    quantx_kernel<<<2048, 256>>>(x);

    WS ws;
    ws.W[0] = Wq;  ws.t1[0] = wq1;
    ws.W[1] = Wk;  ws.t1[1] = wk1;
    ws.W[2] = Wv;  ws.t1[2] = wv1;
    ws.W[3] = Wo;  ws.t1[3] = wo1;
    wsplit4_kernel<<<dim3(512, 1, 4), 256>>>(ws);

    dim3 blk(128);
    dim3 gproj(DIM / 64, MROWS / 64, 1);

    GP q  = {x1, wq1, 0, 0, bq, 1.f / 32.f, 1.f, DIM, 0, q1, nullptr, nullptr};
    GP k  = {x1, wk1, 0, 0, bk, 1.f / 32.f, 1.f, DIM, 5, k1, nullptr, nullptr};
    GP v  = {x1, wv1, 0, 0, bv, 1.f / 32.f, 1.f, DIM, 1, vt1, nullptr, nullptr};
    GP s  = {q1, k1, (long)SEQ * HDIM, (long)SEQ * HDIM,
             nullptr, 0.125f, 1.f, HDIM, 3, p1, nullptr, rsum};
    GP av = {p1, vt1, (long)SEQ * SEQ, (long)HDIM * SEQ,
             nullptr, 1.f, 4.f, SEQ, 4, a1, nullptr, rsum};
    GP o  = {a1, wo1, 0, 0, bo, 1.f / 128.f, 1.f, DIM, 2, nullptr, out, nullptr};

    gemm_kernel<<<gproj, blk, SMEM>>>(q);
    gemm_kernel<<<gproj, blk, SMEM>>>(k);
    gemm_kernel<<<gproj, blk, SMEM>>>(v);
    gemm_kernel<<<dim3(SEQ / 64, SEQ / 64, BH), blk, SMEM>>>(s);
    gemm_kernel<<<dim3(1, SEQ / 64, BH), blk, SMEM>>>(av);
    gemm_kernel<<<gproj, blk, SMEM>>>(o);
}

// round 17
// speedup vs baseline: 3.0204x; 1.1678x over previous
#include <cuda_runtime.h>
#include <cuda_fp16.h>
#include <math.h>
#include <stdint.h>

#define BH    32
#define SEQ   2048
#define DIM   1024
#define NH    16
#define HDIM  64
#define MROWS 4096

// ---------------- device scratch (fragment-tiled, single fp16) ----------------
__device__ __align__(16) __half g_x1[MROWS * DIM];                     // A-tiled
__device__ __align__(16) __half g_Wq1[DIM * DIM], g_Wk1[DIM * DIM];    // B-tiled x32
__device__ __align__(16) __half g_Wv1[DIM * DIM], g_Wo1[DIM * DIM];
__device__ __align__(16) __half g_Q1[BH * SEQ * HDIM];                 // A-tiled
__device__ __align__(16) __half g_K1[BH * SEQ * HDIM];                 // B-tiled
__device__ __align__(16) __half g_Vt1[BH * HDIM * SEQ];                // B-tiled (hd-major)
__device__ __align__(16) __half g_P1[(size_t)BH * SEQ * SEQ];          // A-tiled
__device__ float g_rowsum[BH * SEQ];
__device__ __align__(16) __half g_A1[MROWS * DIM];                     // A-tiled x4

// ---------------- helpers ----------------
__device__ __forceinline__ uint32_t smem_u32(const void* p) {
    uint32_t a;
    asm("{ .reg .u64 t; cvta.to.shared.u64 t, %1; cvt.u32.u64 %0, t; }" : "=r"(a) : "l"(p));
    return a;
}
__device__ __forceinline__ void cp16(uint32_t s, const void* g) {
    asm volatile("cp.async.cg.shared.global [%0], [%1], 16;" :: "r"(s), "l"(g));
}
__device__ __forceinline__ void mma_f16(float* d, const uint32_t* a, const uint32_t* b) {
    asm volatile(
        "mma.sync.aligned.m16n8k16.row.col.f32.f16.f16.f32 "
        "{%0,%1,%2,%3}, {%4,%5,%6,%7}, {%8,%9}, {%0,%1,%2,%3};"
        : "+f"(d[0]), "+f"(d[1]), "+f"(d[2]), "+f"(d[3])
        : "r"(a[0]), "r"(a[1]), "r"(a[2]), "r"(a[3]), "r"(b[0]), "r"(b[1]));
}
#define LDS128(r, addr) \
    asm volatile("ld.shared.v4.b32 {%0,%1,%2,%3}, [%4];" \
        : "=r"((r)[0]), "=r"((r)[1]), "=r"((r)[2]), "=r"((r)[3]) : "r"(addr))

__device__ __forceinline__ uint32_t pack2(float v0, float v1) {
    __half h0 = __float2half_rn(v0), h1 = __float2half_rn(v1);
    return ((uint32_t)__half_as_ushort(h1) << 16) | __half_as_ushort(h0);
}

// fragment-tiled index maps
__device__ __forceinline__ size_t atile(int m, int k, int ktiles) {
    int r = m & 15, c = k & 15;
    return ((((size_t)(m >> 4)) * ktiles + (k >> 4)) << 8)
         + ((((r & 7) << 2) + ((c & 7) >> 1)) << 3)
         + (((r >> 3) + ((c >> 3) << 1)) << 1) + (c & 1);
}
__device__ __forceinline__ size_t btile(int n, int k, int ktiles) {
    int nn = n & 15, kk = k & 15;
    return ((((size_t)(n >> 4)) * ktiles + (k >> 4)) << 8)
         + ((((nn & 7) << 2) + ((kk & 7) >> 1)) << 3)
         + (((kk >> 3) + ((nn >> 3) << 1)) << 1) + (kk & 1);
}

// ---------------- GEMM parameter block ----------------
struct GP {
    const __half *A, *B;
    long bStrideA, bStrideB;
    const float* bias;
    float cs;          // dequant multiplier on raw accum
    float scale;       // extra out multiplier (storage scale)
    int Ktot, mode;
    __half *outp;
    float *outF, *rowsum;
};

// ---------------- conversion kernels ----------------
__global__ __launch_bounds__(256) void quantx_kernel(const float* __restrict__ x) {
    int slot = blockIdx.x * 256 + threadIdx.x;
    int tile = slot >> 5, lane = slot & 31;
    int tm = tile >> 6, tk = tile & 63;
    int rg = lane >> 2, tq = lane & 3;
    const float* b0 = x + (size_t)(tm * 16 + rg) * DIM + tk * 16 + tq * 2;
    float2 f00 = *(const float2*)b0;
    float2 f10 = *(const float2*)(b0 + 8 * DIM);
    float2 f01 = *(const float2*)(b0 + 8);
    float2 f11 = *(const float2*)(b0 + 8 * DIM + 8);
    uint4 hv;
    hv.x = pack2(f00.x, f00.y);
    hv.y = pack2(f10.x, f10.y);
    hv.z = pack2(f01.x, f01.y);
    hv.w = pack2(f11.x, f11.y);
    ((uint4*)g_x1)[slot] = hv;
}

struct WS { const float* W[4]; __half* t1[4]; };
__global__ __launch_bounds__(256) void wsplit4_kernel(WS ws) {
    int slot = blockIdx.x * 256 + threadIdx.x;
    int tile = slot >> 5, lane = slot & 31;
    int tn = tile >> 6, tk = tile & 63;
    int g = lane >> 2, tq = lane & 3;
    const float* W = ws.W[blockIdx.z];
    const float* c0 = W + (size_t)(tk * 16 + tq * 2) * DIM + tn * 16 + g;
    uint4 hv;
    hv.x = pack2(c0[0] * 32.f,           c0[DIM] * 32.f);
    hv.y = pack2(c0[8 * DIM] * 32.f,     c0[9 * DIM] * 32.f);
    hv.z = pack2(c0[8] * 32.f,           c0[DIM + 8] * 32.f);
    hv.w = pack2(c0[8 * DIM + 8] * 32.f, c0[9 * DIM + 8] * 32.f);
    ((uint4*)ws.t1[blockIdx.z])[slot] = hv;
}

// ---------------- GEMM: CTA 128x64, 4 warps (warp tile 32x64), single fp16 --------
// modes: 0 Q (A-tiled), 5 K (B-tiled), 1 Vt (B-tiled transposed),
//        2 fp32 out (+bias), 3 exp->P (A-tiled) + rowsum, 4 attn (A-tiled, x scale)
__global__ __launch_bounds__(128, 4) void gemm_kernel(GP P)
{
    extern __shared__ char smem[];
    constexpr int STAGE = 12288;   // A 8K | B 4K

    const int tid = threadIdx.x;
    const int w = tid >> 5, lane = tid & 31;
    const int g = lane >> 2, t = lane & 3;
    const int bx = blockIdx.x, by = blockIdx.y, bz = blockIdx.z;
    const __half* Ap = P.A + (size_t)bz * P.bStrideA;
    const __half* Bp = P.B + (size_t)bz * P.bStrideB;

    const int m0 = by * 128, n0 = bx * 64;
    const int ktiles = P.Ktot >> 4;
    const int nch = P.Ktot >> 5;
    const uint32_t sb = smem_u32(smem);

    float acc[2][8][4];
#pragma unroll
    for (int i = 0; i < 2; i++)
#pragma unroll
        for (int j = 0; j < 8; j++)
#pragma unroll
            for (int k = 0; k < 4; k++) acc[i][j][k] = 0.f;

    // precomputed stage-load pointers (advance by constant 512 elems per chunk)
    const __half* aptr[4];
    uint32_t aoffs[4];
#pragma unroll
    for (int j = 0; j < 4; j++) {
        int i = tid + 128 * j, tl = i >> 5, s = i & 31;
        aptr[j] = Ap + (((size_t)((m0 >> 4) + (tl >> 1))) * ktiles + (tl & 1)) * 256 + s * 8;
        aoffs[j] = tl * 512 + s * 16;
    }
    const __half* bptr[2];
    uint32_t boffs[2];
#pragma unroll
    for (int j = 0; j < 2; j++) {
        int i = tid + 128 * j, tl = i >> 5, s = i & 31;
        bptr[j] = Bp + (((size_t)((n0 >> 4) + (tl >> 1))) * ktiles + (tl & 1)) * 256 + s * 8;
        boffs[j] = 8192 + tl * 512 + s * 16;
    }

    auto stage_load = [&](int buf) {
        const uint32_t so = sb + buf * STAGE;
#pragma unroll
        for (int j = 0; j < 4; j++) { cp16(so + aoffs[j], aptr[j]); aptr[j] += 512; }
#pragma unroll
        for (int j = 0; j < 2; j++) { cp16(so + boffs[j], bptr[j]); bptr[j] += 512; }
        asm volatile("cp.async.commit_group;");
    };

    stage_load(0);
    for (int c = 0; c < nch; c++) {
        const int buf = c & 1;
        if (c + 1 < nch) {
            stage_load(buf ^ 1);
            asm volatile("cp.async.wait_group 1;");
        } else {
            asm volatile("cp.async.wait_group 0;");
        }
        __syncthreads();

        const uint32_t so = sb + buf * STAGE;
#pragma unroll
        for (int ks = 0; ks < 2; ks++) {
            uint32_t a4[2][4], b4[4][4];
#pragma unroll
            for (int mt = 0; mt < 2; mt++) {
                uint32_t a = so + ((((w * 2 + mt) << 1) + ks) << 9) + (lane << 4);
                LDS128(a4[mt], a);
            }
#pragma unroll
            for (int p2 = 0; p2 < 4; p2++) {
                uint32_t b = so + 8192 + (((p2 << 1) + ks) << 9) + (lane << 4);
                LDS128(b4[p2], b);
            }
#pragma unroll
            for (int mt = 0; mt < 2; mt++)
#pragma unroll
                for (int nt = 0; nt < 8; nt++)
                    mma_f16(acc[mt][nt], a4[mt], &b4[nt >> 1][(nt & 1) << 1]);
        }
        __syncthreads();
    }

    // ---------------- epilogue ----------------
    const int mode = P.mode;
    if (mode == 3) {
        float rs[2][2] = {};
#pragma unroll
        for (int mt = 0; mt < 2; mt++)
#pragma unroll
            for (int nt = 0; nt < 8; nt++)
#pragma unroll
                for (int p = 0; p < 2; p++) {
                    float e0 = __expf(acc[mt][nt][2 * p + 0] * P.cs);
                    float e1 = __expf(acc[mt][nt][2 * p + 1] * P.cs);
                    acc[mt][nt][2 * p + 0] = e0;
                    acc[mt][nt][2 * p + 1] = e1;
                    rs[mt][p] += e0 + e1;
                }
#pragma unroll
        for (int mt = 0; mt < 2; mt++)
#pragma unroll
            for (int p = 0; p < 2; p++) {
                int row = m0 + w * 32 + mt * 16 + g + 8 * p;
#pragma unroll
                for (int nt = 0; nt < 8; nt++) {
                    int col = n0 + nt * 8 + 2 * t;
                    size_t e = (size_t)bz * SEQ * SEQ + atile(row, col, 128);
                    *(uint32_t*)(P.outp + e)
                        = pack2(acc[mt][nt][2 * p + 0], acc[mt][nt][2 * p + 1]);
                }
                float s2 = rs[mt][p];
                s2 += __shfl_xor_sync(0xffffffffu, s2, 1);
                s2 += __shfl_xor_sync(0xffffffffu, s2, 2);
                if (t == 0) atomicAdd(&P.rowsum[bz * SEQ + row], s2);
            }
        return;
    }

#pragma unroll
    for (int mt = 0; mt < 2; mt++)
#pragma unroll
        for (int nt = 0; nt < 8; nt++)
#pragma unroll
            for (int p = 0; p < 2; p++) {
                int row = m0 + w * 32 + mt * 16 + g + 8 * p;
                int col = n0 + nt * 8 + 2 * t;
                float v0 = acc[mt][nt][2 * p + 0];
                float v1 = acc[mt][nt][2 * p + 1];
                if (mode == 0) {          // Q: A-tiled head-split
                    int b = row >> 11, sq = row & (SEQ - 1);
                    int h = col >> 6, hd = col & (HDIM - 1);
                    v0 = v0 * P.cs + P.bias[col];
                    v1 = v1 * P.cs + P.bias[col + 1];
                    size_t e = (size_t)(b * NH + h) * SEQ * HDIM + atile(sq, hd, 4);
                    *(uint32_t*)(P.outp + e) = pack2(v0, v1);
                } else if (mode == 5) {   // K: B-tiled head-split
                    int b = row >> 11, sq = row & (SEQ - 1);
                    int h = col >> 6, hd = col & (HDIM - 1);
                    v0 = v0 * P.cs + P.bias[col];
                    v1 = v1 * P.cs + P.bias[col + 1];
                    size_t e = (size_t)(b * NH + h) * SEQ * HDIM + btile(sq, hd, 4);
                    *(uint32_t*)(P.outp + e) = pack2(v0, v1);
                } else if (mode == 1) {   // Vt: B-tiled transposed
                    int b = row >> 11, sq = row & (SEQ - 1);
                    v0 = v0 * P.cs + P.bias[col];
                    v1 = v1 * P.cs + P.bias[col + 1];
#pragma unroll
                    for (int e2 = 0; e2 < 2; e2++) {
                        int cc = col + e2;
                        int h = cc >> 6, hd = cc & (HDIM - 1);
                        size_t e = (size_t)(b * NH + h) * HDIM * SEQ + btile(hd, sq, 128);
                        P.outp[e] = __float2half_rn(e2 ? v1 : v0);
                    }
                } else if (mode == 2) {   // fp32 out + bias
                    *(float2*)(P.outF + (size_t)row * DIM + col)
                        = make_float2(v0 * P.cs + P.bias[col], v1 * P.cs + P.bias[col + 1]);
                } else {                  // mode 4: attn A-tiled, x4 storage scale
                    float inv = P.scale / P.rowsum[bz * SEQ + row];
                    v0 *= inv;
                    v1 *= inv;
                    int b = bz >> 4, h = bz & (NH - 1);
                    int gm = b * SEQ + row, gc = h * HDIM + col;
                    size_t e = atile(gm, gc, 64);
                    *(uint32_t*)(P.outp + e) = pack2(v0, v1);
                }
            }
}

// ---------------- host ----------------
static void* sym(const void* s) { void* p; cudaGetSymbolAddress(&p, s); return p; }

extern "C" void kernel_launch(void* const* d_in, const int* in_sizes, int n_in,
                              void* d_out, int out_size)
{
    const float* x  = (const float*)d_in[0];
    const float* Wq = (const float*)d_in[1];
    const float* bq = (const float*)d_in[2];
    const float* Wk = (const float*)d_in[3];
    const float* bk = (const float*)d_in[4];
    const float* Wv = (const float*)d_in[5];
    const float* bv = (const float*)d_in[6];
    const float* Wo = (const float*)d_in[7];
    const float* bo = (const float*)d_in[8];
    float* out = (float*)d_out;

    constexpr int SMEM = 2 * 12288;   // 24576
    cudaFuncSetAttribute(gemm_kernel, cudaFuncAttributeMaxDynamicSharedMemorySize, SMEM);

    __half *x1 = (__half*)sym(g_x1);
    __half *wq1 = (__half*)sym(g_Wq1), *wk1 = (__half*)sym(g_Wk1);
    __half *wv1 = (__half*)sym(g_Wv1), *wo1 = (__half*)sym(g_Wo1);
    __half *q1 = (__half*)sym(g_Q1), *k1 = (__half*)sym(g_K1), *vt1 = (__half*)sym(g_Vt1);
    __half *p1 = (__half*)sym(g_P1), *a1 = (__half*)sym(g_A1);
    float* rsum = (float*)sym(g_rowsum);

    cudaMemsetAsync(rsum, 0, BH * SEQ * sizeof(float), 0);

    quantx_kernel<<<2048, 256>>>(x);

    WS ws;
    ws.W[0] = Wq;  ws.t1[0] = wq1;
    ws.W[1] = Wk;  ws.t1[1] = wk1;
    ws.W[2] = Wv;  ws.t1[2] = wv1;
    ws.W[3] = Wo;  ws.t1[3] = wo1;
    wsplit4_kernel<<<dim3(512, 1, 4), 256>>>(ws);

    dim3 blk(128);
    dim3 gproj(DIM / 64, MROWS / 128, 1);   // 16 x 32

    GP q  = {x1, wq1, 0, 0, bq, 1.f / 32.f, 1.f, DIM, 0, q1, nullptr, nullptr};
    GP k  = {x1, wk1, 0, 0, bk, 1.f / 32.f, 1.f, DIM, 5, k1, nullptr, nullptr};
    GP v  = {x1, wv1, 0, 0, bv, 1.f / 32.f, 1.f, DIM, 1, vt1, nullptr, nullptr};
    GP s  = {q1, k1, (long)SEQ * HDIM, (long)SEQ * HDIM,
             nullptr, 0.125f, 1.f, HDIM, 3, p1, nullptr, rsum};
    GP av = {p1, vt1, (long)SEQ * SEQ, (long)HDIM * SEQ,
             nullptr, 1.f, 4.f, SEQ, 4, a1, nullptr, rsum};
    GP o  = {a1, wo1, 0, 0, bo, 1.f / 128.f, 1.f, DIM, 2, nullptr, out, nullptr};

    gemm_kernel<<<gproj, blk, SMEM>>>(q);
    gemm_kernel<<<gproj, blk, SMEM>>>(k);
    gemm_kernel<<<gproj, blk, SMEM>>>(v);
    gemm_kernel<<<dim3(SEQ / 64, SEQ / 128, BH), blk, SMEM>>>(s);
    gemm_kernel<<<dim3(1, SEQ / 128, BH), blk, SMEM>>>(av);
    gemm_kernel<<<gproj, blk, SMEM>>>(o);
}